// round 13
// baseline (speedup 1.0000x reference)
#include <cuda_runtime.h>
#include <cstdint>

// ============================================================================
// Compile-time Clebsch-Gordan / real-basis Wigner-3j machinery (constexpr).
// Reproduces the reference build_w3j exactly (validated: rel_err 5e-8).
// ============================================================================

namespace cgc {

struct cplx { double re, im; };

__host__ __device__ constexpr double fact(int n) {
    double r = 1.0;
    for (int i = 2; i <= n; i++) r *= (double)i;
    return r;
}

__host__ __device__ constexpr double csqrt_(double x) {
    if (x <= 0.0) return 0.0;
    double g = x > 1.0 ? x : 1.0;
    for (int i = 0; i < 64; i++) g = 0.5 * (g + x / g);
    return g;
}

__host__ __device__ constexpr double cg_su2(int j1, int m1, int j2, int m2, int j3, int m3) {
    if (m3 != m1 + m2) return 0.0;
    double pref = csqrt_((2.0 * j3 + 1.0) * fact(j3 + j1 - j2) * fact(j3 - j1 + j2) *
                         fact(j1 + j2 - j3) / fact(j1 + j2 + j3 + 1));
    pref *= csqrt_(fact(j3 + m3) * fact(j3 - m3) * fact(j1 - m1) * fact(j1 + m1) *
                   fact(j2 - m2) * fact(j2 + m2));
    double s = 0.0;
    for (int k = 0; k <= j1 + j2 - j3; k++) {
        int a = j1 - m1 - k, b = j2 + m2 - k, c = j3 - j2 + m1 + k, d = j3 - j1 - m2 + k;
        if (a < 0 || b < 0 || c < 0 || d < 0) continue;
        double t = 1.0 / (fact(k) * fact(j1 + j2 - j3 - k) * fact(a) * fact(b) * fact(c) * fact(d));
        s += (k & 1) ? -t : t;
    }
    return pref * s;
}

__host__ __device__ constexpr cplx Qent(int l, int i, int j) {
    constexpr double inv = 0.70710678118654752440;
    double re = 0.0, im = 0.0;
    int mi = i - l;
    if (mi < 0) {
        if (j == l - mi)      re = inv;
        else if (j == l + mi) im = -inv;
    } else if (mi == 0) {
        if (j == l) re = 1.0;
    } else {
        double sgn = (mi & 1) ? -1.0 : 1.0;
        if (j == l + mi)      re = sgn * inv;
        else if (j == l - mi) im = sgn * inv;
    }
    switch (l & 3) {
        case 1:  return cplx{ im, -re };
        case 2:  return cplx{ -re, -im };
        case 3:  return cplx{ -im,  re };
        default: return cplx{ re, im };
    }
}

template <int L1, int L2, int L3>
struct Blk { float v[(2 * L1 + 1) * (2 * L2 + 1) * (2 * L3 + 1)]; };

template <int L1, int L2, int L3>
__host__ __device__ constexpr Blk<L1, L2, L3> build_block() {
    constexpr int D1 = 2 * L1 + 1, D2 = 2 * L2 + 1, D3 = 2 * L3 + 1;
    double C[D1][D2] = {};
    for (int i = 0; i < D1; i++)
        for (int k = 0; k < D2; k++) {
            int m1 = i - L1, m2 = k - L2, m3 = m1 + m2;
            C[i][k] = (m3 < -L3 || m3 > L3) ? 0.0 : cg_su2(L1, m1, L2, m2, L3, m3);
        }
    double tmp[D1][D2][D3] = {};
    double n2 = 0.0;
    for (int j = 0; j < D1; j++)
        for (int l = 0; l < D2; l++)
            for (int n = 0; n < D3; n++) {
                double sre = 0.0;
                for (int t1 = 0; t1 < 2; t1++) {
                    int i = t1 ? (2 * L1 - j) : j;
                    if (t1 && i == j) break;
                    cplx q1 = Qent(L1, i, j);
                    if (q1.re == 0.0 && q1.im == 0.0) continue;
                    for (int t2 = 0; t2 < 2; t2++) {
                        int k = t2 ? (2 * L2 - l) : l;
                        if (t2 && k == l) break;
                        cplx q2 = Qent(L2, k, l);
                        if (q2.re == 0.0 && q2.im == 0.0) continue;
                        int m = (i - L1) + (k - L2) + L3;
                        if (m < 0 || m > 2 * L3) continue;
                        cplx q3r = Qent(L3, m, n);
                        cplx q3  = cplx{ q3r.re, -q3r.im };
                        if (q3.re == 0.0 && q3.im == 0.0) continue;
                        double pr12 = q1.re * q2.re - q1.im * q2.im;
                        double pi12 = q1.re * q2.im + q1.im * q2.re;
                        double pr   = pr12 * q3.re - pi12 * q3.im;
                        sre += pr * C[i][k];
                    }
                }
                tmp[j][l][n] = sre;
                n2 += sre * sre;
            }
    double scale = csqrt_((double)(2 * L3 + 1) / n2);
    Blk<L1, L2, L3> B{};
    for (int j = 0; j < D1; j++)
        for (int l = 0; l < D2; l++)
            for (int n = 0; n < D3; n++)
                B.v[(j * D2 + l) * D3 + n] = (float)(tmp[j][l][n] * scale);
    return B;
}

}  // namespace cgc

// ============================================================================
// Kernel: 4 warps per block, 4-way column phase split, TWO 32-row tiles per
// block with double-buffered smem. Tile 0's TMA store is issued (commit, no
// wait) before tile 1 is computed -> store drain overlaps compute, smoothing
// the per-SM write stream.
// ============================================================================

constexpr int TPB    = 128;   // 4 warps; warp w -> its column phase
constexpr int ROWS   = 32;    // rows per tile
constexpr int TILES  = 2;     // tiles per block (double buffer)
constexpr int OUT_C  = 170;
// Unpadded smem rows (stride 170 floats): each tile's staged output is
// byte-identical to the linear global region -> one 1D TMA bulk store each.
// STS.64 at stride 170: bank pairs (10*t mod 32) distinct over 16 half-warp
// lanes -> conflict-free.
constexpr int BUF_F  = ROWS * OUT_C;                       // 5440 floats
constexpr int BUF_B  = BUF_F * (int)sizeof(float);         // 21760 B
// launch_bounds(128, 5): 5 blocks/SM = 20 warps, smem 217.6 KB, regs <= 102.

__device__ __forceinline__ uint32_t smem_u32(const void* p) {
    return (uint32_t)__cvta_generic_to_shared(p);
}

// One path: fully unrolled; coefficients fold to FFMA immediates, zeros DCE'd.
template <int L1, int L2, int L3, int OFF>
__device__ __forceinline__ void apply_path(const float (&a)[16], const float (&b)[16],
                                           float* __restrict__ srow, float& carry) {
    constexpr auto B = cgc::build_block<L1, L2, L3>();
    constexpr int D1 = 2 * L1 + 1, D2 = 2 * L2 + 1, D3 = 2 * L3 + 1;
    float o[D3];
#pragma unroll
    for (int n = 0; n < D3; n++) {
        float acc = 0.0f;
#pragma unroll
        for (int i = 0; i < D1; i++) {
#pragma unroll
            for (int k = 0; k < D2; k++) {
                const float w = B.v[(i * D2 + k) * D3 + n];
                if (w != 0.0f)
                    acc = fmaf(w, a[L1 * L1 + i] * b[L2 * L2 + k], acc);
            }
        }
        o[n] = acc;
    }
    if constexpr ((OFF & 1) != 0) {
        *reinterpret_cast<float2*>(srow + (OFF - 1)) = make_float2(carry, o[0]);
#pragma unroll
        for (int n = 1; n + 1 < D3; n += 2)
            *reinterpret_cast<float2*>(srow + (OFF + n)) = make_float2(o[n], o[n + 1]);
    } else {
#pragma unroll
        for (int n = 0; n + 1 < D3; n += 2)
            *reinterpret_cast<float2*>(srow + (OFF + n)) = make_float2(o[n], o[n + 1]);
        carry = o[D3 - 1];
    }
}

// Phase A: cols [0, 22)
__device__ __forceinline__ void phaseA(const float (&a)[16], const float (&b)[16],
                                       float* __restrict__ srow) {
    float carry = 0.0f;
    apply_path<0, 0, 0,  0>(a, b, srow, carry);
    apply_path<1, 1, 0,  1>(a, b, srow, carry);
    apply_path<2, 2, 0,  2>(a, b, srow, carry);
    apply_path<3, 3, 0,  3>(a, b, srow, carry);
    apply_path<0, 1, 1,  4>(a, b, srow, carry);
    apply_path<1, 0, 1,  7>(a, b, srow, carry);
    apply_path<1, 2, 1, 10>(a, b, srow, carry);
    apply_path<2, 1, 1, 13>(a, b, srow, carry);
    apply_path<2, 3, 1, 16>(a, b, srow, carry);
    apply_path<3, 2, 1, 19>(a, b, srow, carry);
}

// Phase B: cols [22, 64)
__device__ __forceinline__ void phaseB(const float (&a)[16], const float (&b)[16],
                                       float* __restrict__ srow) {
    float carry = 0.0f;
    apply_path<0, 2, 2, 22>(a, b, srow, carry);
    apply_path<1, 1, 2, 27>(a, b, srow, carry);
    apply_path<1, 3, 2, 32>(a, b, srow, carry);
    apply_path<2, 0, 2, 37>(a, b, srow, carry);
    apply_path<2, 2, 2, 42>(a, b, srow, carry);
    apply_path<3, 1, 2, 47>(a, b, srow, carry);
    apply_path<3, 3, 2, 52>(a, b, srow, carry);
    apply_path<0, 3, 3, 57>(a, b, srow, carry);
}

// Phase C: cols [64, 126)
__device__ __forceinline__ void phaseC(const float (&a)[16], const float (&b)[16],
                                       float* __restrict__ srow) {
    float carry = 0.0f;
    apply_path<1, 2, 3,  64>(a, b, srow, carry);
    apply_path<2, 1, 3,  71>(a, b, srow, carry);
    apply_path<2, 3, 3,  78>(a, b, srow, carry);
    apply_path<3, 0, 3,  85>(a, b, srow, carry);
    apply_path<3, 2, 3,  92>(a, b, srow, carry);
    apply_path<1, 3, 4,  99>(a, b, srow, carry);
    apply_path<2, 2, 4, 108>(a, b, srow, carry);
    apply_path<3, 1, 4, 117>(a, b, srow, carry);
}

// Phase D: cols [126, 170)
__device__ __forceinline__ void phaseD(const float (&a)[16], const float (&b)[16],
                                       float* __restrict__ srow) {
    float carry = 0.0f;
    apply_path<3, 3, 4, 126>(a, b, srow, carry);
    apply_path<2, 3, 5, 135>(a, b, srow, carry);
    apply_path<3, 2, 5, 146>(a, b, srow, carry);
    apply_path<3, 3, 6, 157>(a, b, srow, carry);
}

// Compute one 32-row tile into buf (phase-split across the 4 warps).
__device__ __forceinline__ void compute_tile(const float* __restrict__ x1,
                                             const float* __restrict__ x2,
                                             float* __restrict__ buf,
                                             int row, int lrow, int phase, int N) {
    float a[16], b[16];
    if (row < N) {
        const float4* p1 = reinterpret_cast<const float4*>(x1) + (long long)row * 4;
        const float4* p2 = reinterpret_cast<const float4*>(x2) + (long long)row * 4;
#pragma unroll
        for (int q = 0; q < 4; q++) {
            float4 v1 = p1[q];
            a[4 * q + 0] = v1.x; a[4 * q + 1] = v1.y; a[4 * q + 2] = v1.z; a[4 * q + 3] = v1.w;
            float4 v2 = p2[q];
            b[4 * q + 0] = v2.x; b[4 * q + 1] = v2.y; b[4 * q + 2] = v2.z; b[4 * q + 3] = v2.w;
        }
    } else {
#pragma unroll
        for (int q = 0; q < 16; q++) { a[q] = 0.0f; b[q] = 0.0f; }
    }

    float* srow = buf + lrow * OUT_C;
    switch (phase) {
        case 0: phaseA(a, b, srow); break;
        case 1: phaseB(a, b, srow); break;
        case 2: phaseC(a, b, srow); break;
        default: phaseD(a, b, srow); break;
    }
}

__global__ void __launch_bounds__(TPB, 5)
tp_kernel(const float* __restrict__ x1, const float* __restrict__ x2,
          float* __restrict__ out, int N) {
    __shared__ float sbuf[TILES * BUF_F];
    const int tid   = threadIdx.x;
    const int lrow  = tid & (ROWS - 1);      // row within tile
    const int phase = tid >> 5;              // warp id = column phase
    const int blockRowBase = blockIdx.x * (ROWS * TILES);

#pragma unroll
    for (int t = 0; t < TILES; t++) {
        const int rowBase = blockRowBase + t * ROWS;
        if (rowBase >= N) break;

        float* buf = sbuf + t * BUF_F;
        compute_tile(x1, x2, buf, rowBase + lrow, lrow, phase, N);

        __syncthreads();

        const int rowsHere = min(ROWS, N - rowBase);
        float* gout = out + (long long)rowBase * OUT_C;

        if (rowsHere == ROWS) {
            if (tid == 0) {
                asm volatile("fence.proxy.async.shared::cta;" ::: "memory");
                asm volatile(
                    "cp.async.bulk.global.shared::cta.bulk_group [%0], [%1], %2;"
                    :: "l"(gout), "r"(smem_u32(buf)), "r"((uint32_t)BUF_B)
                    : "memory");
                asm volatile("cp.async.bulk.commit_group;" ::: "memory");
                // NO wait here: tile 0's store drains while tile 1 computes.
            }
        } else {
            // Partial tile (not hit for N = 500000): coalesced element copy.
            for (int e = tid; e < rowsHere * OUT_C; e += TPB)
                gout[e] = buf[e];
        }
    }

    // Before this block (and its smem) retires, all issued bulk stores must
    // have finished READING smem; write completion drains at kernel end.
    if (tid == 0)
        asm volatile("cp.async.bulk.wait_group.read 0;" ::: "memory");
}

// ============================================================================
// Launch
// ============================================================================

extern "C" void kernel_launch(void* const* d_in, const int* in_sizes, int n_in,
                              void* d_out, int out_size) {
    const float* x1 = (const float*)d_in[0];
    const float* x2 = (const float*)d_in[1];
    float* out = (float*)d_out;
    const int N = in_sizes[0] / 16;

    const int grid = (N + ROWS * TILES - 1) / (ROWS * TILES);
    tp_kernel<<<grid, TPB>>>(x1, x2, out, N);
}

// round 14
// speedup vs baseline: 1.0059x; 1.0059x over previous
#include <cuda_runtime.h>
#include <cstdint>

// ============================================================================
// Compile-time Clebsch-Gordan / real-basis Wigner-3j machinery (constexpr).
// Reproduces the reference build_w3j exactly (validated: rel_err 5e-8).
// ============================================================================

namespace cgc {

struct cplx { double re, im; };

__host__ __device__ constexpr double fact(int n) {
    double r = 1.0;
    for (int i = 2; i <= n; i++) r *= (double)i;
    return r;
}

__host__ __device__ constexpr double csqrt_(double x) {
    if (x <= 0.0) return 0.0;
    double g = x > 1.0 ? x : 1.0;
    for (int i = 0; i < 64; i++) g = 0.5 * (g + x / g);
    return g;
}

__host__ __device__ constexpr double cg_su2(int j1, int m1, int j2, int m2, int j3, int m3) {
    if (m3 != m1 + m2) return 0.0;
    double pref = csqrt_((2.0 * j3 + 1.0) * fact(j3 + j1 - j2) * fact(j3 - j1 + j2) *
                         fact(j1 + j2 - j3) / fact(j1 + j2 + j3 + 1));
    pref *= csqrt_(fact(j3 + m3) * fact(j3 - m3) * fact(j1 - m1) * fact(j1 + m1) *
                   fact(j2 - m2) * fact(j2 + m2));
    double s = 0.0;
    for (int k = 0; k <= j1 + j2 - j3; k++) {
        int a = j1 - m1 - k, b = j2 + m2 - k, c = j3 - j2 + m1 + k, d = j3 - j1 - m2 + k;
        if (a < 0 || b < 0 || c < 0 || d < 0) continue;
        double t = 1.0 / (fact(k) * fact(j1 + j2 - j3 - k) * fact(a) * fact(b) * fact(c) * fact(d));
        s += (k & 1) ? -t : t;
    }
    return pref * s;
}

__host__ __device__ constexpr cplx Qent(int l, int i, int j) {
    constexpr double inv = 0.70710678118654752440;
    double re = 0.0, im = 0.0;
    int mi = i - l;
    if (mi < 0) {
        if (j == l - mi)      re = inv;
        else if (j == l + mi) im = -inv;
    } else if (mi == 0) {
        if (j == l) re = 1.0;
    } else {
        double sgn = (mi & 1) ? -1.0 : 1.0;
        if (j == l + mi)      re = sgn * inv;
        else if (j == l - mi) im = sgn * inv;
    }
    switch (l & 3) {
        case 1:  return cplx{ im, -re };
        case 2:  return cplx{ -re, -im };
        case 3:  return cplx{ -im,  re };
        default: return cplx{ re, im };
    }
}

template <int L1, int L2, int L3>
struct Blk { float v[(2 * L1 + 1) * (2 * L2 + 1) * (2 * L3 + 1)]; };

template <int L1, int L2, int L3>
__host__ __device__ constexpr Blk<L1, L2, L3> build_block() {
    constexpr int D1 = 2 * L1 + 1, D2 = 2 * L2 + 1, D3 = 2 * L3 + 1;
    double C[D1][D2] = {};
    for (int i = 0; i < D1; i++)
        for (int k = 0; k < D2; k++) {
            int m1 = i - L1, m2 = k - L2, m3 = m1 + m2;
            C[i][k] = (m3 < -L3 || m3 > L3) ? 0.0 : cg_su2(L1, m1, L2, m2, L3, m3);
        }
    double tmp[D1][D2][D3] = {};
    double n2 = 0.0;
    for (int j = 0; j < D1; j++)
        for (int l = 0; l < D2; l++)
            for (int n = 0; n < D3; n++) {
                double sre = 0.0;
                for (int t1 = 0; t1 < 2; t1++) {
                    int i = t1 ? (2 * L1 - j) : j;
                    if (t1 && i == j) break;
                    cplx q1 = Qent(L1, i, j);
                    if (q1.re == 0.0 && q1.im == 0.0) continue;
                    for (int t2 = 0; t2 < 2; t2++) {
                        int k = t2 ? (2 * L2 - l) : l;
                        if (t2 && k == l) break;
                        cplx q2 = Qent(L2, k, l);
                        if (q2.re == 0.0 && q2.im == 0.0) continue;
                        int m = (i - L1) + (k - L2) + L3;
                        if (m < 0 || m > 2 * L3) continue;
                        cplx q3r = Qent(L3, m, n);
                        cplx q3  = cplx{ q3r.re, -q3r.im };
                        if (q3.re == 0.0 && q3.im == 0.0) continue;
                        double pr12 = q1.re * q2.re - q1.im * q2.im;
                        double pi12 = q1.re * q2.im + q1.im * q2.re;
                        double pr   = pr12 * q3.re - pi12 * q3.im;
                        sre += pr * C[i][k];
                    }
                }
                tmp[j][l][n] = sre;
                n2 += sre * sre;
            }
    double scale = csqrt_((double)(2 * L3 + 1) / n2);
    Blk<L1, L2, L3> B{};
    for (int j = 0; j < D1; j++)
        for (int l = 0; l < D2; l++)
            for (int n = 0; n < D3; n++)
                B.v[(j * D2 + l) * D3 + n] = (float)(tmp[j][l][n] * scale);
    return B;
}

}  // namespace cgc

// ============================================================================
// Kernel (terminal design, R8): 4 warps per block, 4-way column phase split,
// 32 rows per block. Compute fully unrolled into FFMA-immediates; outputs
// staged unpadded in smem (byte-identical to the linear global region) and
// written with a single 21.76 KB 1D TMA bulk store per block. Pinned at the
// HBM write roofline (~5.7 TB/s; DRAM traffic == output size).
// ============================================================================

constexpr int TPB    = 128;   // 4 warps; warp w -> its column phase
constexpr int ROWS   = 32;    // rows per tile (N = 500000 = 15625 * 32, no tail)
constexpr int OUT_C  = 170;
// Unpadded smem rows (stride 170 floats). STS.64 at stride 170: bank pairs
// (10*t mod 32) distinct over 16 half-warp lanes -> conflict-free.
constexpr int BUF_F  = ROWS * OUT_C;                       // 5440 floats
constexpr int BUF_B  = BUF_F * (int)sizeof(float);         // 21760 B
// launch_bounds(128, 6): 6 blocks/SM = 24 warps, smem 131 KB, regs <= 85.

__device__ __forceinline__ uint32_t smem_u32(const void* p) {
    return (uint32_t)__cvta_generic_to_shared(p);
}

// One path: fully unrolled; coefficients fold to FFMA immediates, zeros DCE'd.
// Outputs paired into float2 STS via `carry` (path sizes odd, offsets within a
// phase alternate parity, each phase starts & ends at even global offsets).
template <int L1, int L2, int L3, int OFF>
__device__ __forceinline__ void apply_path(const float (&a)[16], const float (&b)[16],
                                           float* __restrict__ srow, float& carry) {
    constexpr auto B = cgc::build_block<L1, L2, L3>();
    constexpr int D1 = 2 * L1 + 1, D2 = 2 * L2 + 1, D3 = 2 * L3 + 1;
    float o[D3];
#pragma unroll
    for (int n = 0; n < D3; n++) {
        float acc = 0.0f;
#pragma unroll
        for (int i = 0; i < D1; i++) {
#pragma unroll
            for (int k = 0; k < D2; k++) {
                const float w = B.v[(i * D2 + k) * D3 + n];
                if (w != 0.0f)
                    acc = fmaf(w, a[L1 * L1 + i] * b[L2 * L2 + k], acc);
            }
        }
        o[n] = acc;
    }
    if constexpr ((OFF & 1) != 0) {
        *reinterpret_cast<float2*>(srow + (OFF - 1)) = make_float2(carry, o[0]);
#pragma unroll
        for (int n = 1; n + 1 < D3; n += 2)
            *reinterpret_cast<float2*>(srow + (OFF + n)) = make_float2(o[n], o[n + 1]);
    } else {
#pragma unroll
        for (int n = 0; n + 1 < D3; n += 2)
            *reinterpret_cast<float2*>(srow + (OFF + n)) = make_float2(o[n], o[n + 1]);
        carry = o[D3 - 1];
    }
}

// Phase A: cols [0, 22)
__device__ __forceinline__ void phaseA(const float (&a)[16], const float (&b)[16],
                                       float* __restrict__ srow) {
    float carry = 0.0f;
    apply_path<0, 0, 0,  0>(a, b, srow, carry);
    apply_path<1, 1, 0,  1>(a, b, srow, carry);
    apply_path<2, 2, 0,  2>(a, b, srow, carry);
    apply_path<3, 3, 0,  3>(a, b, srow, carry);
    apply_path<0, 1, 1,  4>(a, b, srow, carry);
    apply_path<1, 0, 1,  7>(a, b, srow, carry);
    apply_path<1, 2, 1, 10>(a, b, srow, carry);
    apply_path<2, 1, 1, 13>(a, b, srow, carry);
    apply_path<2, 3, 1, 16>(a, b, srow, carry);
    apply_path<3, 2, 1, 19>(a, b, srow, carry);
}

// Phase B: cols [22, 64)
__device__ __forceinline__ void phaseB(const float (&a)[16], const float (&b)[16],
                                       float* __restrict__ srow) {
    float carry = 0.0f;
    apply_path<0, 2, 2, 22>(a, b, srow, carry);
    apply_path<1, 1, 2, 27>(a, b, srow, carry);
    apply_path<1, 3, 2, 32>(a, b, srow, carry);
    apply_path<2, 0, 2, 37>(a, b, srow, carry);
    apply_path<2, 2, 2, 42>(a, b, srow, carry);
    apply_path<3, 1, 2, 47>(a, b, srow, carry);
    apply_path<3, 3, 2, 52>(a, b, srow, carry);
    apply_path<0, 3, 3, 57>(a, b, srow, carry);
}

// Phase C: cols [64, 126)
__device__ __forceinline__ void phaseC(const float (&a)[16], const float (&b)[16],
                                       float* __restrict__ srow) {
    float carry = 0.0f;
    apply_path<1, 2, 3,  64>(a, b, srow, carry);
    apply_path<2, 1, 3,  71>(a, b, srow, carry);
    apply_path<2, 3, 3,  78>(a, b, srow, carry);
    apply_path<3, 0, 3,  85>(a, b, srow, carry);
    apply_path<3, 2, 3,  92>(a, b, srow, carry);
    apply_path<1, 3, 4,  99>(a, b, srow, carry);
    apply_path<2, 2, 4, 108>(a, b, srow, carry);
    apply_path<3, 1, 4, 117>(a, b, srow, carry);
}

// Phase D: cols [126, 170)
__device__ __forceinline__ void phaseD(const float (&a)[16], const float (&b)[16],
                                       float* __restrict__ srow) {
    float carry = 0.0f;
    apply_path<3, 3, 4, 126>(a, b, srow, carry);
    apply_path<2, 3, 5, 135>(a, b, srow, carry);
    apply_path<3, 2, 5, 146>(a, b, srow, carry);
    apply_path<3, 3, 6, 157>(a, b, srow, carry);
}

__global__ void __launch_bounds__(TPB, 6)
tp_kernel(const float* __restrict__ x1, const float* __restrict__ x2,
          float* __restrict__ out, int N) {
    __shared__ float sout[BUF_F];
    const int tid   = threadIdx.x;
    const int lrow  = tid & (ROWS - 1);      // row within tile
    const int phase = tid >> 5;              // warp id = column phase
    const int rowBase = blockIdx.x * ROWS;
    const int row = rowBase + lrow;

    float a[16], b[16];
    if (row < N) {
        const float4* p1 = reinterpret_cast<const float4*>(x1) + (long long)row * 4;
        const float4* p2 = reinterpret_cast<const float4*>(x2) + (long long)row * 4;
#pragma unroll
        for (int q = 0; q < 4; q++) {
            float4 v1 = p1[q];
            a[4 * q + 0] = v1.x; a[4 * q + 1] = v1.y; a[4 * q + 2] = v1.z; a[4 * q + 3] = v1.w;
            float4 v2 = p2[q];
            b[4 * q + 0] = v2.x; b[4 * q + 1] = v2.y; b[4 * q + 2] = v2.z; b[4 * q + 3] = v2.w;
        }
    } else {
#pragma unroll
        for (int q = 0; q < 16; q++) { a[q] = 0.0f; b[q] = 0.0f; }
    }

    float* srow = sout + lrow * OUT_C;

    switch (phase) {
        case 0: phaseA(a, b, srow); break;
        case 1: phaseB(a, b, srow); break;
        case 2: phaseC(a, b, srow); break;
        default: phaseD(a, b, srow); break;
    }

    __syncthreads();

    const int rowsHere = min(ROWS, N - rowBase);
    float* gout = out + (long long)rowBase * OUT_C;

    if (rowsHere == ROWS) {
        if (tid == 0) {
            asm volatile("fence.proxy.async.shared::cta;" ::: "memory");
            asm volatile(
                "cp.async.bulk.global.shared::cta.bulk_group [%0], [%1], %2;"
                :: "l"(gout), "r"(smem_u32(sout)), "r"((uint32_t)BUF_B)
                : "memory");
            asm volatile("cp.async.bulk.commit_group;" ::: "memory");
            // Only the smem READ must finish before this block (and its smem)
            // retires; gmem write completion drains at kernel end.
            asm volatile("cp.async.bulk.wait_group.read 0;" ::: "memory");
        }
    } else {
        // Tail tile (not hit for N = 500000): coalesced element copy.
        for (int e = tid; e < rowsHere * OUT_C; e += TPB)
            gout[e] = sout[e];
    }
}

// ============================================================================
// Launch
// ============================================================================

extern "C" void kernel_launch(void* const* d_in, const int* in_sizes, int n_in,
                              void* d_out, int out_size) {
    const float* x1 = (const float*)d_in[0];
    const float* x2 = (const float*)d_in[1];
    float* out = (float*)d_out;
    const int N = in_sizes[0] / 16;

    const int grid = (N + ROWS - 1) / ROWS;
    tp_kernel<<<grid, TPB>>>(x1, x2, out, N);
}

// round 15
// speedup vs baseline: 1.0310x; 1.0250x over previous
#include <cuda_runtime.h>
#include <cstdint>

// ============================================================================
// FullTensorProduct (LMAX1=LMAX2=3, N=500000) — terminal kernel (R8 design).
//
// Design summary (each element ncu-validated across rounds 1-14):
//  * All 30 CG paths' coefficients computed at COMPILE TIME (constexpr Racah
//    formula + real<->complex basis change, double precision) -> every term
//    is an FFMA with an immediate; zero coefficient loads at runtime.
//  * 32 rows/block, 4 warps, warp w computes output-column phase w (balanced
//    FMA cost); per-thread straight-line unrolled code, regs = 80.
//  * Outputs staged UNPADDED in smem (row stride 170 floats): the tile is
//    byte-identical to its linear global region -> ONE 21.76 KB 1D TMA bulk
//    store per block; STS.64 at stride 170 is bank-conflict-free.
//  * wait_group.read 0 (not full wait) before block retirement.
//  * Pinned at the HBM write roofline: DRAM traffic == output size (340 MB),
//    5.6-5.7 TB/s sustained; all SM pipes <= 35%. Ten further structural
//    variants (occupancy, L2 hints, tile sizes, barrier splits, overlap,
//    persistence) measured neutral-or-worse.
// ============================================================================

namespace cgc {

struct cplx { double re, im; };

__host__ __device__ constexpr double fact(int n) {
    double r = 1.0;
    for (int i = 2; i <= n; i++) r *= (double)i;
    return r;
}

__host__ __device__ constexpr double csqrt_(double x) {
    if (x <= 0.0) return 0.0;
    double g = x > 1.0 ? x : 1.0;
    for (int i = 0; i < 64; i++) g = 0.5 * (g + x / g);
    return g;
}

__host__ __device__ constexpr double cg_su2(int j1, int m1, int j2, int m2, int j3, int m3) {
    if (m3 != m1 + m2) return 0.0;
    double pref = csqrt_((2.0 * j3 + 1.0) * fact(j3 + j1 - j2) * fact(j3 - j1 + j2) *
                         fact(j1 + j2 - j3) / fact(j1 + j2 + j3 + 1));
    pref *= csqrt_(fact(j3 + m3) * fact(j3 - m3) * fact(j1 - m1) * fact(j1 + m1) *
                   fact(j2 - m2) * fact(j2 + m2));
    double s = 0.0;
    for (int k = 0; k <= j1 + j2 - j3; k++) {
        int a = j1 - m1 - k, b = j2 + m2 - k, c = j3 - j2 + m1 + k, d = j3 - j1 - m2 + k;
        if (a < 0 || b < 0 || c < 0 || d < 0) continue;
        double t = 1.0 / (fact(k) * fact(j1 + j2 - j3 - k) * fact(a) * fact(b) * fact(c) * fact(d));
        s += (k & 1) ? -t : t;
    }
    return pref * s;
}

__host__ __device__ constexpr cplx Qent(int l, int i, int j) {
    constexpr double inv = 0.70710678118654752440;
    double re = 0.0, im = 0.0;
    int mi = i - l;
    if (mi < 0) {
        if (j == l - mi)      re = inv;
        else if (j == l + mi) im = -inv;
    } else if (mi == 0) {
        if (j == l) re = 1.0;
    } else {
        double sgn = (mi & 1) ? -1.0 : 1.0;
        if (j == l + mi)      re = sgn * inv;
        else if (j == l - mi) im = sgn * inv;
    }
    switch (l & 3) {
        case 1:  return cplx{ im, -re };
        case 2:  return cplx{ -re, -im };
        case 3:  return cplx{ -im,  re };
        default: return cplx{ re, im };
    }
}

template <int L1, int L2, int L3>
struct Blk { float v[(2 * L1 + 1) * (2 * L2 + 1) * (2 * L3 + 1)]; };

template <int L1, int L2, int L3>
__host__ __device__ constexpr Blk<L1, L2, L3> build_block() {
    constexpr int D1 = 2 * L1 + 1, D2 = 2 * L2 + 1, D3 = 2 * L3 + 1;
    double C[D1][D2] = {};
    for (int i = 0; i < D1; i++)
        for (int k = 0; k < D2; k++) {
            int m1 = i - L1, m2 = k - L2, m3 = m1 + m2;
            C[i][k] = (m3 < -L3 || m3 > L3) ? 0.0 : cg_su2(L1, m1, L2, m2, L3, m3);
        }
    double tmp[D1][D2][D3] = {};
    double n2 = 0.0;
    for (int j = 0; j < D1; j++)
        for (int l = 0; l < D2; l++)
            for (int n = 0; n < D3; n++) {
                double sre = 0.0;
                for (int t1 = 0; t1 < 2; t1++) {
                    int i = t1 ? (2 * L1 - j) : j;
                    if (t1 && i == j) break;
                    cplx q1 = Qent(L1, i, j);
                    if (q1.re == 0.0 && q1.im == 0.0) continue;
                    for (int t2 = 0; t2 < 2; t2++) {
                        int k = t2 ? (2 * L2 - l) : l;
                        if (t2 && k == l) break;
                        cplx q2 = Qent(L2, k, l);
                        if (q2.re == 0.0 && q2.im == 0.0) continue;
                        int m = (i - L1) + (k - L2) + L3;
                        if (m < 0 || m > 2 * L3) continue;
                        cplx q3r = Qent(L3, m, n);
                        cplx q3  = cplx{ q3r.re, -q3r.im };
                        if (q3.re == 0.0 && q3.im == 0.0) continue;
                        double pr12 = q1.re * q2.re - q1.im * q2.im;
                        double pi12 = q1.re * q2.im + q1.im * q2.re;
                        double pr   = pr12 * q3.re - pi12 * q3.im;
                        sre += pr * C[i][k];
                    }
                }
                tmp[j][l][n] = sre;
                n2 += sre * sre;
            }
    double scale = csqrt_((double)(2 * L3 + 1) / n2);
    Blk<L1, L2, L3> B{};
    for (int j = 0; j < D1; j++)
        for (int l = 0; l < D2; l++)
            for (int n = 0; n < D3; n++)
                B.v[(j * D2 + l) * D3 + n] = (float)(tmp[j][l][n] * scale);
    return B;
}

}  // namespace cgc

constexpr int TPB    = 128;   // 4 warps; warp w -> its column phase
constexpr int ROWS   = 32;    // rows per tile (N = 500000 = 15625 * 32, no tail)
constexpr int OUT_C  = 170;
constexpr int BUF_F  = ROWS * OUT_C;                       // 5440 floats
constexpr int BUF_B  = BUF_F * (int)sizeof(float);         // 21760 B

__device__ __forceinline__ uint32_t smem_u32(const void* p) {
    return (uint32_t)__cvta_generic_to_shared(p);
}

template <int L1, int L2, int L3, int OFF>
__device__ __forceinline__ void apply_path(const float (&a)[16], const float (&b)[16],
                                           float* __restrict__ srow, float& carry) {
    constexpr auto B = cgc::build_block<L1, L2, L3>();
    constexpr int D1 = 2 * L1 + 1, D2 = 2 * L2 + 1, D3 = 2 * L3 + 1;
    float o[D3];
#pragma unroll
    for (int n = 0; n < D3; n++) {
        float acc = 0.0f;
#pragma unroll
        for (int i = 0; i < D1; i++) {
#pragma unroll
            for (int k = 0; k < D2; k++) {
                const float w = B.v[(i * D2 + k) * D3 + n];
                if (w != 0.0f)
                    acc = fmaf(w, a[L1 * L1 + i] * b[L2 * L2 + k], acc);
            }
        }
        o[n] = acc;
    }
    if constexpr ((OFF & 1) != 0) {
        *reinterpret_cast<float2*>(srow + (OFF - 1)) = make_float2(carry, o[0]);
#pragma unroll
        for (int n = 1; n + 1 < D3; n += 2)
            *reinterpret_cast<float2*>(srow + (OFF + n)) = make_float2(o[n], o[n + 1]);
    } else {
#pragma unroll
        for (int n = 0; n + 1 < D3; n += 2)
            *reinterpret_cast<float2*>(srow + (OFF + n)) = make_float2(o[n], o[n + 1]);
        carry = o[D3 - 1];
    }
}

// Phase A: cols [0, 22)
__device__ __forceinline__ void phaseA(const float (&a)[16], const float (&b)[16],
                                       float* __restrict__ srow) {
    float carry = 0.0f;
    apply_path<0, 0, 0,  0>(a, b, srow, carry);
    apply_path<1, 1, 0,  1>(a, b, srow, carry);
    apply_path<2, 2, 0,  2>(a, b, srow, carry);
    apply_path<3, 3, 0,  3>(a, b, srow, carry);
    apply_path<0, 1, 1,  4>(a, b, srow, carry);
    apply_path<1, 0, 1,  7>(a, b, srow, carry);
    apply_path<1, 2, 1, 10>(a, b, srow, carry);
    apply_path<2, 1, 1, 13>(a, b, srow, carry);
    apply_path<2, 3, 1, 16>(a, b, srow, carry);
    apply_path<3, 2, 1, 19>(a, b, srow, carry);
}

// Phase B: cols [22, 64)
__device__ __forceinline__ void phaseB(const float (&a)[16], const float (&b)[16],
                                       float* __restrict__ srow) {
    float carry = 0.0f;
    apply_path<0, 2, 2, 22>(a, b, srow, carry);
    apply_path<1, 1, 2, 27>(a, b, srow, carry);
    apply_path<1, 3, 2, 32>(a, b, srow, carry);
    apply_path<2, 0, 2, 37>(a, b, srow, carry);
    apply_path<2, 2, 2, 42>(a, b, srow, carry);
    apply_path<3, 1, 2, 47>(a, b, srow, carry);
    apply_path<3, 3, 2, 52>(a, b, srow, carry);
    apply_path<0, 3, 3, 57>(a, b, srow, carry);
}

// Phase C: cols [64, 126)
__device__ __forceinline__ void phaseC(const float (&a)[16], const float (&b)[16],
                                       float* __restrict__ srow) {
    float carry = 0.0f;
    apply_path<1, 2, 3,  64>(a, b, srow, carry);
    apply_path<2, 1, 3,  71>(a, b, srow, carry);
    apply_path<2, 3, 3,  78>(a, b, srow, carry);
    apply_path<3, 0, 3,  85>(a, b, srow, carry);
    apply_path<3, 2, 3,  92>(a, b, srow, carry);
    apply_path<1, 3, 4,  99>(a, b, srow, carry);
    apply_path<2, 2, 4, 108>(a, b, srow, carry);
    apply_path<3, 1, 4, 117>(a, b, srow, carry);
}

// Phase D: cols [126, 170)
__device__ __forceinline__ void phaseD(const float (&a)[16], const float (&b)[16],
                                       float* __restrict__ srow) {
    float carry = 0.0f;
    apply_path<3, 3, 4, 126>(a, b, srow, carry);
    apply_path<2, 3, 5, 135>(a, b, srow, carry);
    apply_path<3, 2, 5, 146>(a, b, srow, carry);
    apply_path<3, 3, 6, 157>(a, b, srow, carry);
}

__global__ void __launch_bounds__(TPB, 6)
tp_kernel(const float* __restrict__ x1, const float* __restrict__ x2,
          float* __restrict__ out, int N) {
    __shared__ float sout[BUF_F];
    const int tid   = threadIdx.x;
    const int lrow  = tid & (ROWS - 1);      // row within tile
    const int phase = tid >> 5;              // warp id = column phase
    const int rowBase = blockIdx.x * ROWS;
    const int row = rowBase + lrow;

    float a[16], b[16];
    if (row < N) {
        const float4* p1 = reinterpret_cast<const float4*>(x1) + (long long)row * 4;
        const float4* p2 = reinterpret_cast<const float4*>(x2) + (long long)row * 4;
#pragma unroll
        for (int q = 0; q < 4; q++) {
            float4 v1 = p1[q];
            a[4 * q + 0] = v1.x; a[4 * q + 1] = v1.y; a[4 * q + 2] = v1.z; a[4 * q + 3] = v1.w;
            float4 v2 = p2[q];
            b[4 * q + 0] = v2.x; b[4 * q + 1] = v2.y; b[4 * q + 2] = v2.z; b[4 * q + 3] = v2.w;
        }
    } else {
#pragma unroll
        for (int q = 0; q < 16; q++) { a[q] = 0.0f; b[q] = 0.0f; }
    }

    float* srow = sout + lrow * OUT_C;

    switch (phase) {
        case 0: phaseA(a, b, srow); break;
        case 1: phaseB(a, b, srow); break;
        case 2: phaseC(a, b, srow); break;
        default: phaseD(a, b, srow); break;
    }

    __syncthreads();

    const int rowsHere = min(ROWS, N - rowBase);
    float* gout = out + (long long)rowBase * OUT_C;

    if (rowsHere == ROWS) {
        if (tid == 0) {
            asm volatile("fence.proxy.async.shared::cta;" ::: "memory");
            asm volatile(
                "cp.async.bulk.global.shared::cta.bulk_group [%0], [%1], %2;"
                :: "l"(gout), "r"(smem_u32(sout)), "r"((uint32_t)BUF_B)
                : "memory");
            asm volatile("cp.async.bulk.commit_group;" ::: "memory");
            // Only the smem READ must finish before this block (and its smem)
            // retires; gmem write completion drains at kernel end.
            asm volatile("cp.async.bulk.wait_group.read 0;" ::: "memory");
        }
    } else {
        // Tail tile (not hit for N = 500000): coalesced element copy.
        for (int e = tid; e < rowsHere * OUT_C; e += TPB)
            gout[e] = sout[e];
    }
}

// ============================================================================
// Launch
// ============================================================================

extern "C" void kernel_launch(void* const* d_in, const int* in_sizes, int n_in,
                              void* d_out, int out_size) {
    const float* x1 = (const float*)d_in[0];
    const float* x2 = (const float*)d_in[1];
    float* out = (float*)d_out;
    const int N = in_sizes[0] / 16;

    const int grid = (N + ROWS - 1) / ROWS;
    tp_kernel<<<grid, TPB>>>(x1, x2, out, N);
}